// round 3
// baseline (speedup 1.0000x reference)
#include <cuda_runtime.h>
#include <cuda_bf16.h>
#include <cuda_fp16.h>
#include <math.h>

// Problem constants
#define BB 64
#define TT 512
#define ENC 512
#define HH 256
#define G4 1024
#define PD 128
#define XK 640          // POS_DIM + ENC
#define LAB 128
#define VK 768          // HH + ENC
#define BT (BB*TT)      // 32768
#define NOUT (BT*LAB)   // 4194304

// ---------------- device scratch (allocation-free rule: __device__ globals) ----------
__device__ __align__(16) float g_cse[(size_t)BT*ENC];
__device__ __align__(16) float g_X[(size_t)BT*XK];
__device__ __align__(16) float g_z[(size_t)BT*HH];
__device__ __align__(16) float g_gin[(size_t)BT*G4];
__device__ __align__(16) __half g_wTh[256*1024];       // w_hh^T fp16 [k][j] for scan
__device__ __align__(16) float g_hch[(size_t)BT*HH];   // compact chain h
__device__ __align__(16) float g_cch[(size_t)BT*HH];   // compact chain c
__device__ __align__(16) float g_P[(size_t)BT*G4];     // h_chain @ w_hh^T per node
__device__ __align__(16) float g_hs[(size_t)BT*HH];
__device__ __align__(16) float g_logits[(size_t)BT*LAB];
__device__ int g_svec[BT];
__device__ int g_rank[BT];     // LOCAL (per-row) chain rank, -1 if none
__device__ int g_tb[BT];       // per-row sep positions
__device__ int g_nb[BB];
__device__ int g_off[BB];      // global compact offset per row
__device__ int g_total;        // total chain nodes

__device__ __forceinline__ float sigmf(float x) { return 1.0f / (1.0f + expf(-x)); }

// ---- packed f32x2 helpers (Blackwell dual-fp32 pipe; ptxas won't auto-emit) --------
__device__ __forceinline__ unsigned long long fma2(unsigned long long a, unsigned long long b,
                                                   unsigned long long c) {
    unsigned long long d;
    asm("fma.rn.f32x2 %0, %1, %2, %3;" : "=l"(d) : "l"(a), "l"(b), "l"(c));
    return d;
}
__device__ __forceinline__ unsigned long long pack2(float x, float y) {
    unsigned long long r; asm("mov.b64 %0, {%1, %2};" : "=l"(r) : "f"(x), "f"(y)); return r;
}
__device__ __forceinline__ float2 unpack2(unsigned long long v) {
    float2 r; asm("mov.b64 {%0, %1}, %2;" : "=f"(r.x), "=f"(r.y) : "l"(v)); return r;
}

// ---------------- prep: svec, local rank, chain compaction, global offsets ----------
__global__ void k_prep(const int* __restrict__ bd) {
    __shared__ int scnt[BB];
    int b = threadIdx.x;
    if (b < BB) {
        int s = 0, cnt = 0, cur = -1;
        g_svec[b*TT] = 0;
        g_rank[b*TT] = -1;
        #pragma unroll 4
        for (int t = 1; t < TT; t++) {
            if (bd[b*TT + t - 1] == 1) { s = t - 1; g_tb[b*TT + cnt] = t - 1; cur = cnt; cnt++; }
            g_svec[b*TT + t] = s;
            g_rank[b*TT + t] = cur;
        }
        g_nb[b] = cnt;
        scnt[b] = cnt;
    }
    __syncthreads();
    if (threadIdx.x == 0) {
        int o = 0;
        for (int i = 0; i < BB; i++) { g_off[i] = o; o += scnt[i]; }
        g_total = o;
    }
}

// ---------------- transpose w_hh -> fp16 [k][j] for coalesced scan loads -------------
__global__ void k_transpose(const float* __restrict__ whh) {
    int idx = blockIdx.x * blockDim.x + threadIdx.x;  // 262144
    int k = idx >> 10, j = idx & 1023;
    g_wTh[idx] = __float2half(whh[j*HH + k]);
}

// ---------------- exclusive prefix sum over time, per (b, feature) ------------------
__global__ void k_cse(const float* __restrict__ enc) {
    int b = blockIdx.x;
    int d = threadIdx.x;  // 512
    float acc = 0.0f;
    size_t base = (size_t)b * TT * ENC + d;
    #pragma unroll 8
    for (int t = 0; t < TT; t++) {
        size_t idx = base + (size_t)t * ENC;
        g_cse[idx] = acc;
        acc += enc[idx];
    }
}

// ---------------- build X = [pos_emb(128), pooled_mean(512)] ------------------------
__global__ void k_buildX(const int* __restrict__ pos_seq, const float* __restrict__ pos_table) {
    int m = blockIdx.x;             // (b,t)
    int tid = threadIdx.x;          // 640
    int b = m >> 9, t = m & 511;
    int s = g_svec[m];
    if (tid < PD) {
        int p = pos_seq[b*TT + s];
        g_X[(size_t)m*XK + tid] = pos_table[p*PD + tid];
    } else {
        int d = tid - PD;
        float wl = (float)((t - s) > 1 ? (t - s) : 1);
        float v = (g_cse[(size_t)m*ENC + d] - g_cse[((size_t)(b*TT + s))*ENC + d]) / wl;
        g_X[(size_t)m*XK + tid] = v;
    }
}

// ---------------- 128x128x8 SGEMM (double-buffered + f32x2 FMA), C = A @ W^T --------
// MODE 0: z = tanh(X @ cw^T + cb), zeroed at t==0          (K=640)
// MODE 1: gin = z @ w_ih^T + b_ih + b_hh                    (K=256)
// MODE 2: P = hchain @ w_hh^T  (over g_total compact rows)  (K=256)
// MODE 3: logits = [hs, enc] @ lw^T                         (K=768)
template<int MODE>
__global__ void __launch_bounds__(256) gemm_k(const float* __restrict__ W,
                                              const float* __restrict__ b1,
                                              const float* __restrict__ b2,
                                              const float* __restrict__ enc,
                                              int K) {
    __shared__ float As[2][8][128];
    __shared__ float Ws[2][8][128];
    int tid = threadIdx.x;
    int m0 = blockIdx.x * 128, n0 = blockIdx.y * 128;
    if (MODE == 2) { if (m0 >= g_total) return; }
    const float* A = (MODE == 0) ? g_X : (MODE == 1) ? g_z : (MODE == 2) ? g_hch : g_hs;

    int lrow = tid >> 1;
    int lcol = (tid & 1) * 4;
    int tx = tid & 15, ty = tid >> 4;

    unsigned long long acc2[8][4];
    #pragma unroll
    for (int i = 0; i < 8; i++)
        #pragma unroll
        for (int j = 0; j < 4; j++) acc2[i][j] = 0ull;

    auto loadA = [&](int k0) -> float4 {
        if (MODE == 3) {
            int gk = k0 + lcol;
            if (gk < HH) return *reinterpret_cast<const float4*>(g_hs + (size_t)(m0 + lrow)*HH + gk);
            return *reinterpret_cast<const float4*>(enc + (size_t)(m0 + lrow)*ENC + (gk - HH));
        }
        return *reinterpret_cast<const float4*>(A + (size_t)(m0 + lrow)*K + k0 + lcol);
    };
    auto loadW = [&](int k0) -> float4 {
        return *reinterpret_cast<const float4*>(W + (size_t)(n0 + lrow)*K + k0 + lcol);
    };
    auto store = [&](int p, float4 av, float4 wv) {
        As[p][lcol+0][lrow] = av.x; As[p][lcol+1][lrow] = av.y;
        As[p][lcol+2][lrow] = av.z; As[p][lcol+3][lrow] = av.w;
        Ws[p][lcol+0][lrow] = wv.x; Ws[p][lcol+1][lrow] = wv.y;
        Ws[p][lcol+2][lrow] = wv.z; Ws[p][lcol+3][lrow] = wv.w;
    };

    float4 av = loadA(0), wv = loadW(0);
    store(0, av, wv);
    __syncthreads();
    int p = 0;

    for (int k0 = 0; k0 < K; k0 += 8) {
        bool has_next = (k0 + 8 < K);
        if (has_next) { av = loadA(k0 + 8); wv = loadW(k0 + 8); }
        #pragma unroll
        for (int kk = 0; kk < 8; kk++) {
            float4 A0 = *reinterpret_cast<const float4*>(&As[p][kk][ty*4]);
            float4 A1 = *reinterpret_cast<const float4*>(&As[p][kk][64 + ty*4]);
            // W tile as b64 f32x2 pairs straight from 16B smem loads
            double2 W0d = *reinterpret_cast<const double2*>(&Ws[p][kk][tx*4]);
            double2 W1d = *reinterpret_cast<const double2*>(&Ws[p][kk][64 + tx*4]);
            unsigned long long wp0 = __double_as_longlong(W0d.x);
            unsigned long long wp1 = __double_as_longlong(W0d.y);
            unsigned long long wp2 = __double_as_longlong(W1d.x);
            unsigned long long wp3 = __double_as_longlong(W1d.y);
            float a[8] = {A0.x,A0.y,A0.z,A0.w,A1.x,A1.y,A1.z,A1.w};
            #pragma unroll
            for (int i = 0; i < 8; i++) {
                unsigned long long ad = pack2(a[i], a[i]);
                acc2[i][0] = fma2(ad, wp0, acc2[i][0]);
                acc2[i][1] = fma2(ad, wp1, acc2[i][1]);
                acc2[i][2] = fma2(ad, wp2, acc2[i][2]);
                acc2[i][3] = fma2(ad, wp3, acc2[i][3]);
            }
        }
        if (has_next) {
            int q = p ^ 1;
            store(q, av, wv);
            __syncthreads();
            p = q;
        }
    }

    #pragma unroll
    for (int i = 0; i < 8; i++) {
        int m = m0 + ((i < 4) ? ty*4 + i : 64 + ty*4 + i - 4);
        float2 p0 = unpack2(acc2[i][0]), p1 = unpack2(acc2[i][1]);
        float2 p2 = unpack2(acc2[i][2]), p3 = unpack2(acc2[i][3]);
        float vj[8] = {p0.x,p0.y,p1.x,p1.y,p2.x,p2.y,p3.x,p3.y};
        #pragma unroll
        for (int j = 0; j < 8; j++) {
            int n = n0 + ((j < 4) ? tx*4 + j : 64 + tx*4 + j - 4);
            float v = vj[j];
            if (MODE == 0) {
                v = tanhf(v + b1[n]);
                if ((m & 511) == 0) v = 0.0f;
                g_z[(size_t)m*HH + n] = v;
            } else if (MODE == 1) {
                g_gin[(size_t)m*G4 + n] = v + b1[n] + b2[n];
            } else if (MODE == 2) {
                g_P[(size_t)m*G4 + n] = v;
            } else {
                g_logits[(size_t)m*LAB + n] = v;
            }
        }
    }
}

// ---------------- sequential LSTM over compacted boundary chain, 1 CTA/row ----------
__global__ void __launch_bounds__(256) k_scan() {
    int b = blockIdx.x;
    int tid = threadIdx.x;          // 256
    int q = tid >> 6;               // gate quadrant (i,f,g,o)
    int u4 = (tid & 63) << 2;       // 4-unit group
    __shared__ float sh_h[HH];
    __shared__ float sh_g[G4];
    sh_h[tid] = 0.0f;
    float c_reg = 0.0f;
    __syncthreads();
    int n = g_nb[b];
    int off = g_off[b];
    const unsigned int* wb = reinterpret_cast<const unsigned int*>(g_wTh) + ((q*HH + u4) >> 1);
    for (int k = 0; k < n; k++) {
        int t = g_tb[b*TT + k];
        const float* gp = g_gin + ((size_t)(b*TT + t))*G4 + q*HH + u4;
        float4 acc = *reinterpret_cast<const float4*>(gp);
        #pragma unroll 8
        for (int kk = 0; kk < HH; kk++) {
            float hk = sh_h[kk];
            uint2 wv = *reinterpret_cast<const uint2*>(wb + kk*512);   // 4 fp16 weights
            float2 f01 = __half22float2(*reinterpret_cast<const __half2*>(&wv.x));
            float2 f23 = __half22float2(*reinterpret_cast<const __half2*>(&wv.y));
            acc.x += hk*f01.x; acc.y += hk*f01.y; acc.z += hk*f23.x; acc.w += hk*f23.y;
        }
        int gi0 = q*HH + u4;
        sh_g[gi0+0] = acc.x; sh_g[gi0+1] = acc.y; sh_g[gi0+2] = acc.z; sh_g[gi0+3] = acc.w;
        __syncthreads();
        float xi = sh_g[tid], xf = sh_g[HH + tid], xg = sh_g[2*HH + tid], xo = sh_g[3*HH + tid];
        float cc = sigmf(xf)*c_reg + sigmf(xi)*tanhf(xg);
        float hh = sigmf(xo)*tanhf(cc);
        c_reg = cc;
        sh_h[tid] = hh;
        size_t o = ((size_t)(off + k))*HH + tid;
        g_hch[o] = hh;
        g_cch[o] = cc;
        __syncthreads();
    }
}

// ---------------- pointwise LSTM cell over all (b,t), fused carry gather -------------
__global__ void k_lstm() {
    int idx = blockIdx.x * blockDim.x + threadIdx.x;  // BT*256
    int m = idx >> 8, u = idx & 255;
    int b = m >> 9;
    int r = g_rank[m];
    size_t gb = (size_t)m*G4 + u;
    float xi = g_gin[gb], xf = g_gin[gb + HH], xg = g_gin[gb + 2*HH], xo = g_gin[gb + 3*HH];
    float c_sep = 0.0f;
    if (r >= 0) {
        size_t node = (size_t)(g_off[b] + r);
        size_t pb = node*G4 + u;
        xi += g_P[pb]; xf += g_P[pb + HH]; xg += g_P[pb + 2*HH]; xo += g_P[pb + 3*HH];
        c_sep = g_cch[node*HH + u];
    }
    float cc = sigmf(xf)*c_sep + sigmf(xi)*tanhf(xg);
    g_hs[idx] = sigmf(xo)*tanhf(cc);
}

// ---------------- masks + log_softmax + output write --------------------------------
__global__ void k_softmax(const int* __restrict__ lengths, float* __restrict__ out, int dual) {
    int m = blockIdx.x;
    int l = threadIdx.x;   // 128
    int t = m & 511, b = m >> 9;
    float x = g_logits[(size_t)m*LAB + l];
    if (t == 0 && l == 0) x = -1e30f;      // APP_ID = 0 impossible at first char
    if (t >= lengths[b]) x = 0.0f;         // padding rows zeroed before softmax
    float mx = x;
    #pragma unroll
    for (int o = 16; o > 0; o >>= 1) mx = fmaxf(mx, __shfl_xor_sync(0xffffffffu, mx, o));
    __shared__ float sm[4], ssum[4];
    int w = l >> 5;
    if ((l & 31) == 0) sm[w] = mx;
    __syncthreads();
    mx = fmaxf(fmaxf(sm[0], sm[1]), fmaxf(sm[2], sm[3]));
    float e = expf(x - mx);
    float s = e;
    #pragma unroll
    for (int o = 16; o > 0; o >>= 1) s += __shfl_xor_sync(0xffffffffu, s, o);
    if ((l & 31) == 0) ssum[w] = s;
    __syncthreads();
    s = ssum[0] + ssum[1] + ssum[2] + ssum[3];
    float lp = x - mx - logf(s);
    out[(size_t)m*LAB + l] = lp;
    if (dual) out[(size_t)NOUT + (size_t)m*LAB + l] = lp;
}

// ---------------- launch -------------------------------------------------------------
extern "C" void kernel_launch(void* const* d_in, const int* in_sizes, int n_in,
                              void* d_out, int out_size) {
    const float* enc       = (const float*)d_in[0];
    const int*   bd        = (const int*)  d_in[1];
    const int*   pos_seq   = (const int*)  d_in[2];
    const int*   lengths   = (const int*)  d_in[3];
    const float* w_ih      = (const float*)d_in[4];
    const float* w_hh      = (const float*)d_in[5];
    const float* b_ih      = (const float*)d_in[6];
    const float* b_hh      = (const float*)d_in[7];
    const float* pos_table = (const float*)d_in[8];
    const float* linear_w  = (const float*)d_in[9];
    const float* combine_w = (const float*)d_in[10];
    const float* combine_b = (const float*)d_in[11];
    float* out = (float*)d_out;
    int dual = (out_size >= 2*NOUT) ? 1 : 0;

    k_prep<<<1, 64>>>(bd);
    k_transpose<<<512, 512>>>(w_hh);
    k_cse<<<BB, ENC>>>(enc);
    k_buildX<<<BT, XK>>>(pos_seq, pos_table);
    gemm_k<0><<<dim3(BT/128, HH/128),  256>>>(combine_w, combine_b, nullptr, nullptr, XK);
    gemm_k<1><<<dim3(BT/128, G4/128),  256>>>(w_ih,      b_ih,      b_hh,    nullptr, HH);
    k_scan<<<BB, 256>>>();
    gemm_k<2><<<dim3(BT/128, G4/128),  256>>>(w_hh,      nullptr,   nullptr, nullptr, HH);
    k_lstm<<<BT*HH/1024, 1024>>>();
    gemm_k<3><<<dim3(BT/128, LAB/128), 256>>>(linear_w,  nullptr,   nullptr, enc,     VK);
    k_softmax<<<BT, LAB>>>(lengths, out, dual);
}

// round 9
// speedup vs baseline: 1.4144x; 1.4144x over previous
#include <cuda_runtime.h>
#include <cuda_bf16.h>
#include <cuda_fp16.h>
#include <math.h>

// Problem constants
#define BB 64
#define TT 512
#define ENC 512
#define HH 256
#define G4 1024
#define PD 128
#define XK 640          // POS_DIM + ENC
#define LAB 128
#define VK 768          // HH + ENC
#define BT (BB*TT)      // 32768
#define NOUT (BT*LAB)   // 4194304

// ---------------- device scratch (allocation-free rule: __device__ globals) ----------
__device__ __align__(16) float g_cse[(size_t)BT*ENC];
__device__ __align__(16) float g_X[(size_t)BT*XK];
__device__ __align__(16) float g_z[(size_t)BT*HH];
__device__ __align__(16) float g_gin[(size_t)BT*G4];
__device__ __align__(16) __half g_wTh[256*1024];       // w_hh^T fp16 [k][j] for scan
__device__ __align__(16) float g_hch[(size_t)BT*HH];   // compact chain h
__device__ __align__(16) float g_cch[(size_t)BT*HH];   // compact chain c
__device__ __align__(16) float g_P[(size_t)BT*G4];     // h_chain @ w_hh^T per node
__device__ __align__(16) float g_hs[(size_t)BT*HH];
__device__ __align__(16) float g_logits[(size_t)BT*LAB];
__device__ int g_svec[BT];
__device__ int g_rank[BT];     // LOCAL (per-row) chain rank, -1 if none
__device__ int g_tb[BT];       // per-row sep positions
__device__ int g_nb[BB];
__device__ int g_off[BB];      // global compact offset per row
__device__ int g_total;        // total chain nodes

__device__ __forceinline__ float sigmf(float x) { return 1.0f / (1.0f + expf(-x)); }

__device__ __forceinline__ unsigned tf32r(float f) {
    unsigned r; asm("cvt.rna.tf32.f32 %0, %1;" : "=r"(r) : "f"(f)); return r;
}
__device__ __forceinline__ void mma_tf32(float* c, const unsigned* a, unsigned b0, unsigned b1) {
    asm("mma.sync.aligned.m16n8k8.row.col.f32.tf32.tf32.f32 "
        "{%0,%1,%2,%3}, {%4,%5,%6,%7}, {%8,%9}, {%0,%1,%2,%3};"
        : "+f"(c[0]), "+f"(c[1]), "+f"(c[2]), "+f"(c[3])
        : "r"(a[0]), "r"(a[1]), "r"(a[2]), "r"(a[3]), "r"(b0), "r"(b1));
}

// ---------------- prep: svec, local rank, chain compaction, global offsets ----------
__global__ void k_prep(const int* __restrict__ bd) {
    __shared__ int scnt[BB];
    int b = threadIdx.x;
    if (b < BB) {
        int s = 0, cnt = 0, cur = -1;
        g_svec[b*TT] = 0;
        g_rank[b*TT] = -1;
        #pragma unroll 4
        for (int t = 1; t < TT; t++) {
            if (bd[b*TT + t - 1] == 1) { s = t - 1; g_tb[b*TT + cnt] = t - 1; cur = cnt; cnt++; }
            g_svec[b*TT + t] = s;
            g_rank[b*TT + t] = cur;
        }
        g_nb[b] = cnt;
        scnt[b] = cnt;
    }
    __syncthreads();
    if (threadIdx.x == 0) {
        int o = 0;
        for (int i = 0; i < BB; i++) { g_off[i] = o; o += scnt[i]; }
        g_total = o;
    }
}

// ---------------- transpose w_hh -> fp16 [k][j] for coalesced scan loads -------------
__global__ void k_transpose(const float* __restrict__ whh) {
    int idx = blockIdx.x * blockDim.x + threadIdx.x;  // 262144
    int k = idx >> 10, j = idx & 1023;
    g_wTh[idx] = __float2half(whh[j*HH + k]);
}

// ---------------- exclusive prefix sum over time, per (b, feature) ------------------
__global__ void k_cse(const float* __restrict__ enc) {
    int b = blockIdx.x;
    int d = threadIdx.x;  // 512
    float acc = 0.0f;
    size_t base = (size_t)b * TT * ENC + d;
    #pragma unroll 8
    for (int t = 0; t < TT; t++) {
        size_t idx = base + (size_t)t * ENC;
        g_cse[idx] = acc;
        acc += enc[idx];
    }
}

// ---------------- build X = [pos_emb(128), pooled_mean(512)] ------------------------
__global__ void k_buildX(const int* __restrict__ pos_seq, const float* __restrict__ pos_table) {
    int m = blockIdx.x;             // (b,t)
    int tid = threadIdx.x;          // 640
    int b = m >> 9, t = m & 511;
    int s = g_svec[m];
    if (tid < PD) {
        int p = pos_seq[b*TT + s];
        g_X[(size_t)m*XK + tid] = pos_table[p*PD + tid];
    } else {
        int d = tid - PD;
        float wl = (float)((t - s) > 1 ? (t - s) : 1);
        float v = (g_cse[(size_t)m*ENC + d] - g_cse[((size_t)(b*TT + s))*ENC + d]) / wl;
        g_X[(size_t)m*XK + tid] = v;
    }
}

// ---------------- tf32 tensor-core GEMM, C = A @ W^T, 128x128 CTA tile ---------------
// MODE 0: z = tanh(X @ cw^T + cb), zeroed at t==0          (K=640)
// MODE 1: gin = z @ w_ih^T + b_ih + b_hh                    (K=256)
// MODE 2: P = hchain @ w_hh^T  (over g_total compact rows)  (K=256)
// MODE 3: logits = [hs, enc] @ lw^T                         (K=768)
#define KT 16
#define SST 20   // smem row stride (16 + 4 pad): conflict-free for mma fragment pattern
template<int MODE>
__global__ void __launch_bounds__(256, 2) gemm_k(const float* __restrict__ W,
                                                 const float* __restrict__ b1,
                                                 const float* __restrict__ b2,
                                                 const float* __restrict__ enc,
                                                 int K) {
    __shared__ float As[2][128*SST];
    __shared__ float Ws[2][128*SST];
    int tid = threadIdx.x;
    int m0 = blockIdx.x * 128, n0 = blockIdx.y * 128;
    if (MODE == 2) { if (m0 >= g_total) return; }
    const float* A = (MODE == 0) ? g_X : (MODE == 1) ? g_z : (MODE == 2) ? g_hch : g_hs;

    int lr = tid >> 1;            // load row 0..127
    int lc = (tid & 1) * 8;       // load col base 0/8

    auto loadA = [&](int k0, float4& v0, float4& v1) {
        const float* base;
        if (MODE == 3) {
            int gk = k0 + lc;
            if (gk < HH) base = g_hs + (size_t)(m0 + lr)*HH + gk;
            else         base = enc  + (size_t)(m0 + lr)*ENC + (gk - HH);
        } else {
            base = A + (size_t)(m0 + lr)*K + k0 + lc;
        }
        v0 = *reinterpret_cast<const float4*>(base);
        v1 = *reinterpret_cast<const float4*>(base + 4);
    };
    auto loadW = [&](int k0, float4& v0, float4& v1) {
        const float* base = W + (size_t)(n0 + lr)*K + k0 + lc;
        v0 = *reinterpret_cast<const float4*>(base);
        v1 = *reinterpret_cast<const float4*>(base + 4);
    };
    auto stTile = [&](float* dst, float4 v0, float4 v1) {
        int o = lr*SST + lc;
        dst[o+0] = __uint_as_float(tf32r(v0.x)); dst[o+1] = __uint_as_float(tf32r(v0.y));
        dst[o+2] = __uint_as_float(tf32r(v0.z)); dst[o+3] = __uint_as_float(tf32r(v0.w));
        dst[o+4] = __uint_as_float(tf32r(v1.x)); dst[o+5] = __uint_as_float(tf32r(v1.y));
        dst[o+6] = __uint_as_float(tf32r(v1.z)); dst[o+7] = __uint_as_float(tf32r(v1.w));
    };

    int lane = tid & 31, wid = tid >> 5;
    int wm = wid >> 1, wn = wid & 1;       // warp tile: 32(M) x 64(N)
    int qr = lane >> 2, qc = lane & 3;

    float acc[2][8][4];
    #pragma unroll
    for (int i = 0; i < 2; i++)
        #pragma unroll
        for (int j = 0; j < 8; j++)
            #pragma unroll
            for (int e = 0; e < 4; e++) acc[i][j][e] = 0.0f;

    // fragment base offsets (constant across k)
    int aoff = (wm*32 + qr)*SST + qc;       // +i*16*SST, +8*SST, +4, +kk
    int boff = (wn*64 + qr)*SST + qc;       // +j*8*SST, +4, +kk

    float4 av0, av1, wv0, wv1;
    loadA(0, av0, av1); loadW(0, wv0, wv1);
    stTile(As[0], av0, av1); stTile(Ws[0], wv0, wv1);
    __syncthreads();
    int p = 0;
    int nk = K / KT;

    for (int kt = 0; kt < nk; kt++) {
        bool has_next = (kt + 1 < nk);
        if (has_next) { loadA((kt+1)*KT, av0, av1); loadW((kt+1)*KT, wv0, wv1); }
        const float* ap = As[p];
        const float* wp = Ws[p];
        #pragma unroll
        for (int kk = 0; kk < KT; kk += 8) {
            unsigned af[2][4];
            #pragma unroll
            for (int i = 0; i < 2; i++) {
                int o = aoff + i*16*SST + kk;
                af[i][0] = __float_as_uint(ap[o]);
                af[i][1] = __float_as_uint(ap[o + 8*SST]);
                af[i][2] = __float_as_uint(ap[o + 4]);
                af[i][3] = __float_as_uint(ap[o + 8*SST + 4]);
            }
            #pragma unroll
            for (int j = 0; j < 8; j++) {
                int o = boff + j*8*SST + kk;
                unsigned bf0 = __float_as_uint(wp[o]);
                unsigned bf1 = __float_as_uint(wp[o + 4]);
                mma_tf32(acc[0][j], af[0], bf0, bf1);
                mma_tf32(acc[1][j], af[1], bf0, bf1);
            }
        }
        if (has_next) {
            int q = p ^ 1;
            stTile(As[q], av0, av1); stTile(Ws[q], wv0, wv1);
            __syncthreads();
            p = q;
        }
    }

    // epilogue: c0:(r, 2qc) c1:(r, 2qc+1) c2:(r+8, 2qc) c3:(r+8, 2qc+1)
    #pragma unroll
    for (int i = 0; i < 2; i++) {
        #pragma unroll
        for (int j = 0; j < 8; j++) {
            int mb = m0 + wm*32 + i*16 + qr;
            int nb = n0 + wn*64 + j*8 + qc*2;
            #pragma unroll
            for (int e = 0; e < 4; e++) {
                int m = mb + (e >> 1)*8;
                int n = nb + (e & 1);
                float v = acc[i][j][e];
                if (MODE == 0) {
                    v = tanhf(v + b1[n]);
                    if ((m & 511) == 0) v = 0.0f;
                    g_z[(size_t)m*HH + n] = v;
                } else if (MODE == 1) {
                    g_gin[(size_t)m*G4 + n] = v + b1[n] + b2[n];
                } else if (MODE == 2) {
                    g_P[(size_t)m*G4 + n] = v;
                } else {
                    g_logits[(size_t)m*LAB + n] = v;
                }
            }
        }
    }
}

// ------- sequential LSTM over compacted boundary chains, 2 rows per CTA --------------
// Weight loads from L2 are shared across both rows => half the chip L2 traffic.
__global__ void __launch_bounds__(256) k_scan2() {
    int b0 = blockIdx.x * 2;
    int b1 = b0 + 1;
    int tid = threadIdx.x;          // 256
    int q = tid >> 6;               // gate quadrant (i,f,g,o)
    int u4 = (tid & 63) << 2;       // 4-unit group
    __shared__ float sh_h[2][HH];
    __shared__ float sh_g[2][G4];
    sh_h[0][tid] = 0.0f;
    sh_h[1][tid] = 0.0f;
    float c0 = 0.0f, c1 = 0.0f;
    __syncthreads();
    int n0 = g_nb[b0], n1 = g_nb[b1];
    int off0 = g_off[b0], off1 = g_off[b1];
    int nmax = n0 > n1 ? n0 : n1;
    const unsigned int* wb = reinterpret_cast<const unsigned int*>(g_wTh) + ((q*HH + u4) >> 1);
    int gi0 = q*HH + u4;
    for (int k = 0; k < nmax; k++) {
        bool a0 = (k < n0), a1 = (k < n1);
        float4 acc0 = {0,0,0,0}, acc1 = {0,0,0,0};
        if (a0) {
            int t = g_tb[b0*TT + k];
            acc0 = *reinterpret_cast<const float4*>(g_gin + ((size_t)(b0*TT + t))*G4 + gi0);
        }
        if (a1) {
            int t = g_tb[b1*TT + k];
            acc1 = *reinterpret_cast<const float4*>(g_gin + ((size_t)(b1*TT + t))*G4 + gi0);
        }
        #pragma unroll 8
        for (int kk = 0; kk < HH; kk++) {
            float h0 = sh_h[0][kk];
            float h1 = sh_h[1][kk];
            uint2 wv = *reinterpret_cast<const uint2*>(wb + kk*512);   // 4 fp16 weights
            float2 f01 = __half22float2(*reinterpret_cast<const __half2*>(&wv.x));
            float2 f23 = __half22float2(*reinterpret_cast<const __half2*>(&wv.y));
            acc0.x += h0*f01.x; acc0.y += h0*f01.y; acc0.z += h0*f23.x; acc0.w += h0*f23.y;
            acc1.x += h1*f01.x; acc1.y += h1*f01.y; acc1.z += h1*f23.x; acc1.w += h1*f23.y;
        }
        sh_g[0][gi0+0] = acc0.x; sh_g[0][gi0+1] = acc0.y; sh_g[0][gi0+2] = acc0.z; sh_g[0][gi0+3] = acc0.w;
        sh_g[1][gi0+0] = acc1.x; sh_g[1][gi0+1] = acc1.y; sh_g[1][gi0+2] = acc1.z; sh_g[1][gi0+3] = acc1.w;
        __syncthreads();
        if (a0) {
            float xi = sh_g[0][tid], xf = sh_g[0][HH + tid];
            float xg = sh_g[0][2*HH + tid], xo = sh_g[0][3*HH + tid];
            float cc = sigmf(xf)*c0 + sigmf(xi)*tanhf(xg);
            float hh = sigmf(xo)*tanhf(cc);
            c0 = cc;
            sh_h[0][tid] = hh;
            size_t o = ((size_t)(off0 + k))*HH + tid;
            g_hch[o] = hh; g_cch[o] = cc;
        }
        if (a1) {
            float xi = sh_g[1][tid], xf = sh_g[1][HH + tid];
            float xg = sh_g[1][2*HH + tid], xo = sh_g[1][3*HH + tid];
            float cc = sigmf(xf)*c1 + sigmf(xi)*tanhf(xg);
            float hh = sigmf(xo)*tanhf(cc);
            c1 = cc;
            sh_h[1][tid] = hh;
            size_t o = ((size_t)(off1 + k))*HH + tid;
            g_hch[o] = hh; g_cch[o] = cc;
        }
        __syncthreads();
    }
}

// ---------------- pointwise LSTM cell over all (b,t), fused carry gather -------------
__global__ void k_lstm() {
    int idx = blockIdx.x * blockDim.x + threadIdx.x;  // BT*256
    int m = idx >> 8, u = idx & 255;
    int b = m >> 9;
    int r = g_rank[m];
    size_t gb = (size_t)m*G4 + u;
    float xi = g_gin[gb], xf = g_gin[gb + HH], xg = g_gin[gb + 2*HH], xo = g_gin[gb + 3*HH];
    float c_sep = 0.0f;
    if (r >= 0) {
        size_t node = (size_t)(g_off[b] + r);
        size_t pb = node*G4 + u;
        xi += g_P[pb]; xf += g_P[pb + HH]; xg += g_P[pb + 2*HH]; xo += g_P[pb + 3*HH];
        c_sep = g_cch[node*HH + u];
    }
    float cc = sigmf(xf)*c_sep + sigmf(xi)*tanhf(xg);
    g_hs[idx] = sigmf(xo)*tanhf(cc);
}

// ---------------- masks + log_softmax + output write --------------------------------
__global__ void k_softmax(const int* __restrict__ lengths, float* __restrict__ out, int dual) {
    int m = blockIdx.x;
    int l = threadIdx.x;   // 128
    int t = m & 511, b = m >> 9;
    float x = g_logits[(size_t)m*LAB + l];
    if (t == 0 && l == 0) x = -1e30f;      // APP_ID = 0 impossible at first char
    if (t >= lengths[b]) x = 0.0f;         // padding rows zeroed before softmax
    float mx = x;
    #pragma unroll
    for (int o = 16; o > 0; o >>= 1) mx = fmaxf(mx, __shfl_xor_sync(0xffffffffu, mx, o));
    __shared__ float sm[4], ssum[4];
    int w = l >> 5;
    if ((l & 31) == 0) sm[w] = mx;
    __syncthreads();
    mx = fmaxf(fmaxf(sm[0], sm[1]), fmaxf(sm[2], sm[3]));
    float e = expf(x - mx);
    float s = e;
    #pragma unroll
    for (int o = 16; o > 0; o >>= 1) s += __shfl_xor_sync(0xffffffffu, s, o);
    if ((l & 31) == 0) ssum[w] = s;
    __syncthreads();
    s = ssum[0] + ssum[1] + ssum[2] + ssum[3];
    float lp = x - mx - logf(s);
    out[(size_t)m*LAB + l] = lp;
    if (dual) out[(size_t)NOUT + (size_t)m*LAB + l] = lp;
}

// ---------------- launch -------------------------------------------------------------
extern "C" void kernel_launch(void* const* d_in, const int* in_sizes, int n_in,
                              void* d_out, int out_size) {
    const float* enc       = (const float*)d_in[0];
    const int*   bd        = (const int*)  d_in[1];
    const int*   pos_seq   = (const int*)  d_in[2];
    const int*   lengths   = (const int*)  d_in[3];
    const float* w_ih      = (const float*)d_in[4];
    const float* w_hh      = (const float*)d_in[5];
    const float* b_ih      = (const float*)d_in[6];
    const float* b_hh      = (const float*)d_in[7];
    const float* pos_table = (const float*)d_in[8];
    const float* linear_w  = (const float*)d_in[9];
    const float* combine_w = (const float*)d_in[10];
    const float* combine_b = (const float*)d_in[11];
    float* out = (float*)d_out;
    int dual = (out_size >= 2*NOUT) ? 1 : 0;

    k_prep<<<1, 64>>>(bd);
    k_transpose<<<512, 512>>>(w_hh);
    k_cse<<<BB, ENC>>>(enc);
    k_buildX<<<BT, XK>>>(pos_seq, pos_table);
    gemm_k<0><<<dim3(BT/128, 2), 256>>>(combine_w, combine_b, nullptr, nullptr, XK);
    gemm_k<1><<<dim3(BT/128, 8), 256>>>(w_ih,      b_ih,      b_hh,    nullptr, HH);
    k_scan2<<<BB/2, 256>>>();
    gemm_k<2><<<dim3(BT/128, 8), 256>>>(w_hh,      nullptr,   nullptr, nullptr, HH);
    k_lstm<<<BT*HH/1024, 1024>>>();
    gemm_k<3><<<dim3(BT/128, 1), 256>>>(linear_w,  nullptr,   nullptr, enc,     VK);
    k_softmax<<<BT, LAB>>>(lengths, out, dual);
}